// round 11
// baseline (speedup 1.0000x reference)
#include <cuda_runtime.h>
#include <cuda_fp16.h>
#include <cstdint>
#include <cstddef>

// ---------------------------------------------------------------- constants
constexpr int cE = 8, cT = 4096, cD = 2048, cH = 1024;
constexpr size_t X_ELEMS = (size_t)cE * cT * cD;
constexpr size_t W_ELEMS = (size_t)cE * cD * cH;
constexpr size_t H_ELEMS = (size_t)cE * cT * cH;

// ---------------------------------------------------------------- scratch
__device__ __align__(16) __half g_x[X_ELEMS];     // [E][T][D] fp16(x)
__device__ __align__(16) __half g_w1t[W_ELEMS];   // [E][H][D] fp16(w1^T)
__device__ __align__(16) __half g_w3t[W_ELEMS];   // [E][H][D] fp16(w3^T)
__device__ __align__(16) __half g_w2t[W_ELEMS];   // [E][D][H] fp16(w2^T)
__device__ __align__(16) __half g_h[H_ELEMS];     // [E][T][H] fp16(h)

// ---------------------------------------------------------------- PTX helpers
__device__ __forceinline__ uint32_t smem_u32(const void* p) {
    return (uint32_t)__cvta_generic_to_shared(p);
}
__device__ __forceinline__ void cp16(uint32_t dst, const void* src) {
    asm volatile("cp.async.cg.shared.global [%0], [%1], 16;"
                 :: "r"(dst), "l"(src) : "memory");
}
__device__ __forceinline__ void cp_commit() {
    asm volatile("cp.async.commit_group;" ::: "memory");
}
template <int N> __device__ __forceinline__ void cp_wait() {
    asm volatile("cp.async.wait_group %0;" :: "n"(N) : "memory");
}
__device__ __forceinline__ void ldsm4(uint32_t* r, uint32_t addr) {
    asm volatile("ldmatrix.sync.aligned.m8n8.x4.shared.b16 {%0,%1,%2,%3}, [%4];"
                 : "=r"(r[0]), "=r"(r[1]), "=r"(r[2]), "=r"(r[3]) : "r"(addr));
}
__device__ __forceinline__ void mma16816(float* d, const uint32_t* a,
                                         uint32_t b0, uint32_t b1) {
    asm volatile(
        "mma.sync.aligned.m16n8k16.row.col.f32.f16.f16.f32 "
        "{%0,%1,%2,%3}, {%4,%5,%6,%7}, {%8,%9}, {%0,%1,%2,%3};"
        : "+f"(d[0]), "+f"(d[1]), "+f"(d[2]), "+f"(d[3])
        : "r"(a[0]), "r"(a[1]), "r"(a[2]), "r"(a[3]), "r"(b0), "r"(b1));
}
#define SWZ(o) ((o) ^ (((o) >> 3) & 0x70))

// ---------------------------------------------------------------- conversions
__global__ void cvt_x_kernel(const float4* __restrict__ x) {
    size_t i = (size_t)blockIdx.x * blockDim.x + threadIdx.x;
    if (i >= X_ELEMS / 4) return;
    float4 v = x[i];
    uint2 o;
    o.x = ((uint32_t)__half_as_ushort(__float2half(v.y)) << 16)
        | __half_as_ushort(__float2half(v.x));
    o.y = ((uint32_t)__half_as_ushort(__float2half(v.w)) << 16)
        | __half_as_ushort(__float2half(v.z));
    ((uint2*)g_x)[i] = o;
}

// transpose: w [E][R][C] f32 -> out [E][C][R] fp16
__global__ void cvt_tr_kernel(const float* __restrict__ w, int which, int R, int C) {
    __shared__ float tile[32][33];
    int e = blockIdx.z;
    int c0 = blockIdx.x * 32, r0 = blockIdx.y * 32;
    int tx = threadIdx.x, ty = threadIdx.y;
    const float* wp = w + (size_t)e * R * C;
#pragma unroll
    for (int i = ty; i < 32; i += 8)
        tile[i][tx] = wp[(size_t)(r0 + i) * C + c0 + tx];
    __syncthreads();
    __half* oh = (which == 0) ? g_w1t : (which == 1) ? g_w3t : g_w2t;
    oh += (size_t)e * C * R;
#pragma unroll
    for (int i = ty; i < 32; i += 8)
        oh[(size_t)(c0 + i) * R + r0 + tx] = __float2half(tile[tx][i]);
}

// ---------------------------------------------------------------- fused dual GEMM
// G = x@w1, U = x@w3 (pure fp16), h = silu(G)*U -> fp16.
// Register-double-buffered frag pipeline over ks.
constexpr int TILE_B = 128 * 128;            // 128 rows x 128 bytes (64 halfs)
constexpr int STAGES_F = 4;
constexpr int STAGE_F_B = 3 * TILE_B;        // A, B1, B3 = 48 KB
constexpr int SMEM_F = STAGES_F * STAGE_F_B; // 192 KB

__global__ void __launch_bounds__(256, 1) dual_gemm_kernel(
    const __half* __restrict__ A,
    const __half* __restrict__ B1, const __half* __restrict__ B3,
    __half* __restrict__ hout)
{
    constexpr int K = cD, Ntot = cH;
    extern __shared__ __align__(1024) char smraw[];
    const uint32_t smem = smem_u32(smraw);
    const int tid = threadIdx.x;
    const int lane = tid & 31, w = tid >> 5;
    const int wm = (w >> 2) * 64;
    const int wn = (w & 3) * 32;
    const int n0 = blockIdx.x * 128, m0 = blockIdx.y * 128, e = blockIdx.z;

    const int lr = tid >> 1;
    const int lhB = (tid & 1) * 64;
    const __half* aH = A + ((size_t)e * cT + m0 + lr) * K + (lhB >> 1);
    const __half* b1 = B1 + ((size_t)e * Ntot + n0 + lr) * K + (lhB >> 1);
    const __half* b3 = B3 + ((size_t)e * Ntot + n0 + lr) * K + (lhB >> 1);
    const uint32_t lrow = (uint32_t)lr * 128u + (uint32_t)lhB;
    const int nK = K / 64;   // 32

    auto load_stage = [&](int s, int k) {
        uint32_t base = smem + s * STAGE_F_B;
        int k0 = k * 64;
#pragma unroll
        for (int j = 0; j < 4; j++) {
            uint32_t sw = SWZ(lrow + j * 16);
            cp16(base              + sw, aH + k0 + j * 8);
            cp16(base + TILE_B     + sw, b1 + k0 + j * 8);
            cp16(base + 2 * TILE_B + sw, b3 + k0 + j * 8);
        }
    };

    const uint32_t arow = (uint32_t)(lane & 15);
    const uint32_t akb  = (uint32_t)((lane >> 4) * 16);
    const uint32_t brow = (uint32_t)((lane & 7) + ((lane & 16) >> 1));
    const uint32_t bkb  = (uint32_t)(((lane & 8) >> 3) * 16);

    auto ldA = [&](uint32_t base, int ks, uint32_t (*Af)[4]) {
#pragma unroll
        for (int mt = 0; mt < 4; mt++) {
            uint32_t off = SWZ((uint32_t)(wm + mt * 16 + arow) * 128u + ks * 32 + akb);
            ldsm4(Af[mt], base + off);
        }
    };
    auto ldB = [&](uint32_t base, int ks, uint32_t (*Bf)[4]) {
#pragma unroll
        for (int np = 0; np < 2; np++) {
            uint32_t off = SWZ((uint32_t)(wn + np * 16 + brow) * 128u + ks * 32 + bkb);
            ldsm4(Bf[np], base + off);
        }
    };

    float accG[4][4][4] = {};
    float accU[4][4][4] = {};

#pragma unroll
    for (int s = 0; s < STAGES_F - 1; s++) { load_stage(s, s); cp_commit(); }

    for (int kk = 0; kk < nK; kk++) {
        int s = kk % STAGES_F;
        cp_wait<STAGES_F - 2>();
        __syncthreads();
        if (kk + STAGES_F - 1 < nK)
            load_stage((kk + STAGES_F - 1) % STAGES_F, kk + STAGES_F - 1);
        cp_commit();
        uint32_t base = smem + s * STAGE_F_B;

        uint32_t Af[2][4][4], B1f[2][2][4], B3f[2][4];
        ldA(base, 0, Af[0]);
        ldB(base + TILE_B, 0, B1f[0]);
#pragma unroll
        for (int ks = 0; ks < 4; ks++) {
            int cur = ks & 1, nxt = cur ^ 1;
            // issue B3 ldsm; its latency is covered by the G MMAs below
            ldB(base + 2 * TILE_B, ks, B3f);
#pragma unroll
            for (int mt = 0; mt < 4; mt++)
#pragma unroll
                for (int nt = 0; nt < 4; nt++) {
                    int np = nt >> 1, ss = (nt & 1) * 2;
                    mma16816(accG[mt][nt], Af[cur][mt], B1f[cur][np][ss], B1f[cur][np][ss + 1]);
                }
            // prefetch next ks A/B1; latency covered by the U MMAs below
            if (ks < 3) {
                ldA(base, ks + 1, Af[nxt]);
                ldB(base + TILE_B, ks + 1, B1f[nxt]);
            }
#pragma unroll
            for (int mt = 0; mt < 4; mt++)
#pragma unroll
                for (int nt = 0; nt < 4; nt++) {
                    int np = nt >> 1, ss = (nt & 1) * 2;
                    mma16816(accU[mt][nt], Af[cur][mt], B3f[np][ss], B3f[np][ss + 1]);
                }
        }
    }

    // --- epilogue: h = silu(G) * U -> fp16
#pragma unroll
    for (int mt = 0; mt < 4; mt++) {
#pragma unroll
        for (int p = 0; p < 2; p++) {
            int lrow2 = wm + mt * 16 + (lane >> 2) + p * 8;
            size_t gr = ((size_t)e * cT + m0 + lrow2) * (size_t)Ntot;
#pragma unroll
            for (int nt = 0; nt < 4; nt++) {
                int lcol = wn + nt * 8 + (lane & 3) * 2;
                size_t idx = gr + n0 + lcol;
                float gv0 = accG[mt][nt][p * 2], gv1 = accG[mt][nt][p * 2 + 1];
                float uv0 = accU[mt][nt][p * 2], uv1 = accU[mt][nt][p * 2 + 1];
                float h0 = uv0 * gv0 / (1.0f + __expf(-gv0));
                float h1 = uv1 * gv1 / (1.0f + __expf(-gv1));
                __half2 vh;
                vh.x = __float2half(h0);
                vh.y = __float2half(h1);
                *(__half2*)(hout + idx) = vh;
            }
        }
    }
}

// ---------------------------------------------------------------- out GEMM
// out = h @ w2, pure fp16, fp32 out.
// 128 threads, 4 warps of 64x64, CTA 128x128, 3 stages x 32 KB, 2 CTAs/SM.
// Double-buffered frags over ks.
constexpr int STAGES_O = 3;
constexpr int STAGE_O_B = 2 * TILE_B;        // A, B = 32 KB
constexpr int SMEM_O = STAGES_O * STAGE_O_B; // 96 KB

__global__ void __launch_bounds__(128, 2) out_gemm_kernel(
    const __half* __restrict__ A, const __half* __restrict__ B,
    float* __restrict__ out)
{
    constexpr int K = cH, Ntot = cD;
    extern __shared__ __align__(1024) char smraw[];
    const uint32_t smem = smem_u32(smraw);
    const int tid = threadIdx.x;
    const int lane = tid & 31, w = tid >> 5;
    const int wm = (w >> 1) * 64;      // 2 m-warps
    const int wn = (w & 1) * 64;       // 2 n-warps
    const int n0 = blockIdx.x * 128, m0 = blockIdx.y * 128, e = blockIdx.z;

    const int lr = tid;                // 128 threads, one full 128B row each
    const __half* aH = A + ((size_t)e * cT + m0 + lr) * K;
    const __half* bH = B + ((size_t)e * Ntot + n0 + lr) * K;
    const uint32_t lrow = (uint32_t)lr * 128u;
    const int nK = K / 64;   // 16

    auto load_stage = [&](int s, int k) {
        uint32_t base = smem + s * STAGE_O_B;
        int k0 = k * 64;
#pragma unroll
        for (int j = 0; j < 8; j++) {
            uint32_t sw = SWZ(lrow + j * 16);
            cp16(base          + sw, aH + k0 + j * 8);
            cp16(base + TILE_B + sw, bH + k0 + j * 8);
        }
    };

    const uint32_t arow = (uint32_t)(lane & 15);
    const uint32_t akb  = (uint32_t)((lane >> 4) * 16);
    const uint32_t brow = (uint32_t)((lane & 7) + ((lane & 16) >> 1));
    const uint32_t bkb  = (uint32_t)(((lane & 8) >> 3) * 16);

    auto ldA = [&](uint32_t base, int ks, uint32_t (*Af)[4]) {
#pragma unroll
        for (int mt = 0; mt < 4; mt++) {
            uint32_t off = SWZ((uint32_t)(wm + mt * 16 + arow) * 128u + ks * 32 + akb);
            ldsm4(Af[mt], base + off);
        }
    };
    auto ldB = [&](uint32_t base, int ks, uint32_t (*Bf)[4]) {
#pragma unroll
        for (int np = 0; np < 4; np++) {
            uint32_t off = SWZ((uint32_t)(wn + np * 16 + brow) * 128u + ks * 32 + bkb);
            ldsm4(Bf[np], base + off);
        }
    };

    float acc[4][8][4] = {};   // 64x64 warp tile: mt x nt x 4

#pragma unroll
    for (int s = 0; s < STAGES_O - 1; s++) { load_stage(s, s); cp_commit(); }

    for (int kk = 0; kk < nK; kk++) {
        int s = kk % STAGES_O;
        cp_wait<STAGES_O - 2>();
        __syncthreads();
        if (kk + STAGES_O - 1 < nK)
            load_stage((kk + STAGES_O - 1) % STAGES_O, kk + STAGES_O - 1);
        cp_commit();
        uint32_t base = smem + s * STAGE_O_B;

        uint32_t Af[2][4][4], Bf[2][4][4];
        ldA(base, 0, Af[0]);
        ldB(base + TILE_B, 0, Bf[0]);
#pragma unroll
        for (int ks = 0; ks < 4; ks++) {
            int cur = ks & 1, nxt = cur ^ 1;
            if (ks < 3) {
                ldA(base, ks + 1, Af[nxt]);
                ldB(base + TILE_B, ks + 1, Bf[nxt]);
            }
#pragma unroll
            for (int mt = 0; mt < 4; mt++)
#pragma unroll
                for (int nt = 0; nt < 8; nt++) {
                    int np = nt >> 1, ss = (nt & 1) * 2;
                    mma16816(acc[mt][nt], Af[cur][mt], Bf[cur][np][ss], Bf[cur][np][ss + 1]);
                }
        }
    }

#pragma unroll
    for (int mt = 0; mt < 4; mt++) {
#pragma unroll
        for (int p = 0; p < 2; p++) {
            int lrow2 = wm + mt * 16 + (lane >> 2) + p * 8;
            size_t gr = ((size_t)e * cT + m0 + lrow2) * (size_t)Ntot;
#pragma unroll
            for (int nt = 0; nt < 8; nt++) {
                int lcol = wn + nt * 8 + (lane & 3) * 2;
                *(float2*)(out + gr + n0 + lcol) =
                    make_float2(acc[mt][nt][p * 2], acc[mt][nt][p * 2 + 1]);
            }
        }
    }
}

// ---------------------------------------------------------------- host
static inline void* symaddr(const void* s) {
    void* p = nullptr;
    cudaGetSymbolAddress(&p, s);
    return p;
}

extern "C" void kernel_launch(void* const* d_in, const int* in_sizes, int n_in,
                              void* d_out, int out_size) {
    (void)in_sizes; (void)n_in; (void)out_size;
    const float* x  = (const float*)d_in[0];
    const float* w1 = (const float*)d_in[1];
    const float* w2 = (const float*)d_in[2];
    const float* w3 = (const float*)d_in[3];
    float* out = (float*)d_out;

    __half* xh  = (__half*)symaddr(g_x);
    __half* w1t = (__half*)symaddr(g_w1t);
    __half* w3t = (__half*)symaddr(g_w3t);
    __half* w2t = (__half*)symaddr(g_w2t);
    __half* h   = (__half*)symaddr(g_h);

    cudaFuncSetAttribute(dual_gemm_kernel, cudaFuncAttributeMaxDynamicSharedMemorySize, SMEM_F);
    cudaFuncSetAttribute(out_gemm_kernel, cudaFuncAttributeMaxDynamicSharedMemorySize, SMEM_O);

    // 1) x -> fp16
    cvt_x_kernel<<<(int)(X_ELEMS / 4 / 256), 256>>>((const float4*)x);
    // 2-4) transpose weights to K-major fp16
    cvt_tr_kernel<<<dim3(cH / 32, cD / 32, cE), dim3(32, 8)>>>(w1, 0, cD, cH);
    cvt_tr_kernel<<<dim3(cH / 32, cD / 32, cE), dim3(32, 8)>>>(w3, 1, cD, cH);
    cvt_tr_kernel<<<dim3(cD / 32, cH / 32, cE), dim3(32, 8)>>>(w2, 2, cH, cD);
    // 5) fused: G = x@w1, U = x@w3, h = silu(G)*U -> fp16
    dual_gemm_kernel<<<dim3(cH / 128, cT / 128, cE), 256, SMEM_F>>>(
        xh, w1t, w3t, h);
    // 6) out = h @ w2 (fp32)
    out_gemm_kernel<<<dim3(cD / 128, cT / 128, cE), 128, SMEM_O>>>(
        h, w2t, out);
}

// round 13
// speedup vs baseline: 1.0172x; 1.0172x over previous
#include <cuda_runtime.h>
#include <cuda_fp16.h>
#include <cstdint>
#include <cstddef>

// ---------------------------------------------------------------- constants
constexpr int cE = 8, cT = 4096, cD = 2048, cH = 1024;
constexpr size_t X_ELEMS = (size_t)cE * cT * cD;
constexpr size_t W_ELEMS = (size_t)cE * cD * cH;
constexpr size_t H_ELEMS = (size_t)cE * cT * cH;

// ---------------------------------------------------------------- scratch
__device__ __align__(16) __half g_x[X_ELEMS];     // [E][T][D] fp16(x)
__device__ __align__(16) __half g_w1t[W_ELEMS];   // [E][H][D] fp16(w1^T)
__device__ __align__(16) __half g_w3t[W_ELEMS];   // [E][H][D] fp16(w3^T)
__device__ __align__(16) __half g_w2t[W_ELEMS];   // [E][D][H] fp16(w2^T)
__device__ __align__(16) __half g_h[H_ELEMS];     // [E][T][H] fp16(h)

// ---------------------------------------------------------------- PTX helpers
__device__ __forceinline__ uint32_t smem_u32(const void* p) {
    return (uint32_t)__cvta_generic_to_shared(p);
}
__device__ __forceinline__ void cp16(uint32_t dst, const void* src) {
    asm volatile("cp.async.cg.shared.global [%0], [%1], 16;"
                 :: "r"(dst), "l"(src) : "memory");
}
__device__ __forceinline__ void cp_commit() {
    asm volatile("cp.async.commit_group;" ::: "memory");
}
template <int N> __device__ __forceinline__ void cp_wait() {
    asm volatile("cp.async.wait_group %0;" :: "n"(N) : "memory");
}
__device__ __forceinline__ void ldsm4(uint32_t* r, uint32_t addr) {
    asm volatile("ldmatrix.sync.aligned.m8n8.x4.shared.b16 {%0,%1,%2,%3}, [%4];"
                 : "=r"(r[0]), "=r"(r[1]), "=r"(r[2]), "=r"(r[3]) : "r"(addr));
}
__device__ __forceinline__ void mma16816(float* d, const uint32_t* a,
                                         uint32_t b0, uint32_t b1) {
    asm volatile(
        "mma.sync.aligned.m16n8k16.row.col.f32.f16.f16.f32 "
        "{%0,%1,%2,%3}, {%4,%5,%6,%7}, {%8,%9}, {%0,%1,%2,%3};"
        : "+f"(d[0]), "+f"(d[1]), "+f"(d[2]), "+f"(d[3])
        : "r"(a[0]), "r"(a[1]), "r"(a[2]), "r"(a[3]), "r"(b0), "r"(b1));
}
#define SWZ(o) ((o) ^ (((o) >> 3) & 0x70))

// ---------------------------------------------------------------- conversions
__global__ void cvt_x_kernel(const float4* __restrict__ x) {
    size_t i = (size_t)blockIdx.x * blockDim.x + threadIdx.x;
    if (i >= X_ELEMS / 4) return;
    float4 v = x[i];
    uint2 o;
    o.x = ((uint32_t)__half_as_ushort(__float2half(v.y)) << 16)
        | __half_as_ushort(__float2half(v.x));
    o.y = ((uint32_t)__half_as_ushort(__float2half(v.w)) << 16)
        | __half_as_ushort(__float2half(v.z));
    ((uint2*)g_x)[i] = o;
}

// transpose: w [E][R][C] f32 -> out [E][C][R] fp16.
// 64(r) x 32(c) tiles; coalesced 128B loads AND 128B half2 stores.
__global__ void cvt_tr_kernel(const float* __restrict__ w, int which, int R, int C) {
    __shared__ float tile[64][33];
    int e = blockIdx.z;
    int c0 = blockIdx.x * 32, r0 = blockIdx.y * 64;
    int tx = threadIdx.x & 31, ty = threadIdx.x >> 5;   // 256 threads
    const float* wp = w + (size_t)e * R * C;
#pragma unroll
    for (int i = ty; i < 64; i += 8)
        tile[i][tx] = wp[(size_t)(r0 + i) * C + c0 + tx];
    __syncthreads();
    __half* oh = (which == 0) ? g_w1t : (which == 1) ? g_w3t : g_w2t;
    oh += (size_t)e * C * R;
    int cc = threadIdx.x >> 5;   // 0..7
    int r2 = threadIdx.x & 31;   // half2 index over 64 rows
#pragma unroll
    for (int j = 0; j < 4; j++) {
        int c = cc + j * 8;
        __half2 v = __floats2half2_rn(tile[2 * r2][c], tile[2 * r2 + 1][c]);
        *(__half2*)(oh + (size_t)(c0 + c) * R + r0 + 2 * r2) = v;
    }
}

// ---------------------------------------------------------------- fused dual GEMM
// CTA 128(M) x 64(N), 128 threads, 4 warps of 64x32, 3 stages x 32 KB, 2 CTAs/SM.
// G = x@w1, U = x@w3 (pure fp16), h = silu(G)*U -> fp16.
constexpr int A_TILE_F = 128 * 128;              // 16 KB
constexpr int B_TILE_F = 64 * 128;               // 8 KB
constexpr int STAGES_F = 3;
constexpr int STAGE_F_B = A_TILE_F + 2 * B_TILE_F;  // 32 KB
constexpr int SMEM_F = STAGES_F * STAGE_F_B;        // 96 KB

__global__ void __launch_bounds__(128, 2) dual_gemm_kernel(
    const __half* __restrict__ A,
    const __half* __restrict__ B1, const __half* __restrict__ B3,
    __half* __restrict__ hout)
{
    constexpr int K = cD, Ntot = cH;
    extern __shared__ __align__(1024) char smraw[];
    const uint32_t smem = smem_u32(smraw);
    const int tid = threadIdx.x;
    const int lane = tid & 31, w = tid >> 5;
    const int wm = (w >> 1) * 64;      // 2 m-warps
    const int wn = (w & 1) * 32;       // 2 n-warps
    const int n0 = blockIdx.x * 64, m0 = blockIdx.y * 128, e = blockIdx.z;

    // loader: thread t owns A row t; threads 0-63 own B1 row t, 64-127 B3 row t-64
    const __half* aH = A + ((size_t)e * cT + m0 + tid) * K;
    const int brl = tid & 63;
    const __half* bsrc = ((tid >= 64) ? B3 : B1) + ((size_t)e * Ntot + n0 + brl) * K;
    const uint32_t breg = (tid >= 64) ? (uint32_t)(A_TILE_F + B_TILE_F) : (uint32_t)A_TILE_F;
    const uint32_t arow_b = (uint32_t)tid * 128u;
    const uint32_t brow_b = (uint32_t)brl * 128u;
    const int nK = K / 64;   // 32

    auto load_stage = [&](int s, int k) {
        uint32_t base = smem + s * STAGE_F_B;
        int k0 = k * 64;
#pragma unroll
        for (int j = 0; j < 8; j++) {
            cp16(base + SWZ(arow_b + j * 16), aH + k0 + j * 8);
            cp16(base + breg + SWZ(brow_b + j * 16), bsrc + k0 + j * 8);
        }
    };

    const uint32_t arow = (uint32_t)(lane & 15);
    const uint32_t akb  = (uint32_t)((lane >> 4) * 16);
    const uint32_t brow = (uint32_t)((lane & 7) + ((lane & 16) >> 1));
    const uint32_t bkb  = (uint32_t)(((lane & 8) >> 3) * 16);

    float accG[4][4][4] = {};
    float accU[4][4][4] = {};

#pragma unroll
    for (int s = 0; s < STAGES_F - 1; s++) { load_stage(s, s); cp_commit(); }

    for (int kk = 0; kk < nK; kk++) {
        int s = kk % STAGES_F;
        cp_wait<STAGES_F - 2>();
        __syncthreads();
        if (kk + STAGES_F - 1 < nK)
            load_stage((kk + STAGES_F - 1) % STAGES_F, kk + STAGES_F - 1);
        cp_commit();
        uint32_t base = smem + s * STAGE_F_B;
#pragma unroll
        for (int ks = 0; ks < 4; ks++) {
            uint32_t Ah[4][4], Bf[2][4];
#pragma unroll
            for (int mt = 0; mt < 4; mt++) {
                uint32_t off = SWZ((uint32_t)(wm + mt * 16 + arow) * 128u + ks * 32 + akb);
                ldsm4(Ah[mt], base + off);
            }
            // --- G path (w1)
#pragma unroll
            for (int np = 0; np < 2; np++) {
                uint32_t off = SWZ((uint32_t)(wn + np * 16 + brow) * 128u + ks * 32 + bkb);
                ldsm4(Bf[np], base + A_TILE_F + off);
            }
#pragma unroll
            for (int mt = 0; mt < 4; mt++)
#pragma unroll
                for (int nt = 0; nt < 4; nt++) {
                    int np = nt >> 1, ss = (nt & 1) * 2;
                    mma16816(accG[mt][nt], Ah[mt], Bf[np][ss], Bf[np][ss + 1]);
                }
            // --- U path (w3)
#pragma unroll
            for (int np = 0; np < 2; np++) {
                uint32_t off = SWZ((uint32_t)(wn + np * 16 + brow) * 128u + ks * 32 + bkb);
                ldsm4(Bf[np], base + A_TILE_F + B_TILE_F + off);
            }
#pragma unroll
            for (int mt = 0; mt < 4; mt++)
#pragma unroll
                for (int nt = 0; nt < 4; nt++) {
                    int np = nt >> 1, ss = (nt & 1) * 2;
                    mma16816(accU[mt][nt], Ah[mt], Bf[np][ss], Bf[np][ss + 1]);
                }
        }
    }

    // --- epilogue: h = silu(G) * U -> fp16
#pragma unroll
    for (int mt = 0; mt < 4; mt++) {
#pragma unroll
        for (int p = 0; p < 2; p++) {
            int lrow2 = wm + mt * 16 + (lane >> 2) + p * 8;
            size_t gr = ((size_t)e * cT + m0 + lrow2) * (size_t)Ntot;
#pragma unroll
            for (int nt = 0; nt < 4; nt++) {
                int lcol = wn + nt * 8 + (lane & 3) * 2;
                size_t idx = gr + n0 + lcol;
                float gv0 = accG[mt][nt][p * 2], gv1 = accG[mt][nt][p * 2 + 1];
                float uv0 = accU[mt][nt][p * 2], uv1 = accU[mt][nt][p * 2 + 1];
                float h0 = uv0 * gv0 / (1.0f + __expf(-gv0));
                float h1 = uv1 * gv1 / (1.0f + __expf(-gv1));
                __half2 vh;
                vh.x = __float2half(h0);
                vh.y = __float2half(h1);
                *(__half2*)(hout + idx) = vh;
            }
        }
    }
}

// ---------------------------------------------------------------- out GEMM
// out = h @ w2, pure fp16, fp32 out. 3 stages x 32 KB, 2 CTAs/SM. (= R10)
constexpr int TILE_B = 128 * 128;
constexpr int STAGES_O = 3;
constexpr int STAGE_O_B = 2 * TILE_B;        // A, B = 32 KB
constexpr int SMEM_O = STAGES_O * STAGE_O_B; // 96 KB

__global__ void __launch_bounds__(256, 2) out_gemm_kernel(
    const __half* __restrict__ A, const __half* __restrict__ B,
    float* __restrict__ out)
{
    constexpr int K = cH, Ntot = cD;
    extern __shared__ __align__(1024) char smraw[];
    const uint32_t smem = smem_u32(smraw);
    const int tid = threadIdx.x;
    const int lane = tid & 31, w = tid >> 5;
    const int wm = (w >> 2) * 64;
    const int wn = (w & 3) * 32;
    const int n0 = blockIdx.x * 128, m0 = blockIdx.y * 128, e = blockIdx.z;

    const int lr = tid >> 1;
    const int lhB = (tid & 1) * 64;
    const __half* aH = A + ((size_t)e * cT + m0 + lr) * K + (lhB >> 1);
    const __half* bH = B + ((size_t)e * Ntot + n0 + lr) * K + (lhB >> 1);
    const uint32_t lrow = (uint32_t)lr * 128u + (uint32_t)lhB;
    const int nK = K / 64;   // 16

    auto load_stage = [&](int s, int k) {
        uint32_t base = smem + s * STAGE_O_B;
        int k0 = k * 64;
#pragma unroll
        for (int j = 0; j < 4; j++) {
            uint32_t sw = SWZ(lrow + j * 16);
            cp16(base          + sw, aH + k0 + j * 8);
            cp16(base + TILE_B + sw, bH + k0 + j * 8);
        }
    };

    const uint32_t arow = (uint32_t)(lane & 15);
    const uint32_t akb  = (uint32_t)((lane >> 4) * 16);
    const uint32_t brow = (uint32_t)((lane & 7) + ((lane & 16) >> 1));
    const uint32_t bkb  = (uint32_t)(((lane & 8) >> 3) * 16);

    float acc[4][4][4] = {};

#pragma unroll
    for (int s = 0; s < STAGES_O - 1; s++) { load_stage(s, s); cp_commit(); }

    for (int kk = 0; kk < nK; kk++) {
        int s = kk % STAGES_O;
        cp_wait<STAGES_O - 2>();
        __syncthreads();
        if (kk + STAGES_O - 1 < nK)
            load_stage((kk + STAGES_O - 1) % STAGES_O, kk + STAGES_O - 1);
        cp_commit();
        uint32_t base = smem + s * STAGE_O_B;
#pragma unroll
        for (int ks = 0; ks < 4; ks++) {
            uint32_t Ah[4][4], Bh[2][4];
#pragma unroll
            for (int mt = 0; mt < 4; mt++) {
                uint32_t off = SWZ((uint32_t)(wm + mt * 16 + arow) * 128u + ks * 32 + akb);
                ldsm4(Ah[mt], base + off);
            }
#pragma unroll
            for (int np = 0; np < 2; np++) {
                uint32_t off = SWZ((uint32_t)(wn + np * 16 + brow) * 128u + ks * 32 + bkb);
                ldsm4(Bh[np], base + TILE_B + off);
            }
#pragma unroll
            for (int mt = 0; mt < 4; mt++)
#pragma unroll
                for (int nt = 0; nt < 4; nt++) {
                    int np = nt >> 1, ss = (nt & 1) * 2;
                    mma16816(acc[mt][nt], Ah[mt], Bh[np][ss], Bh[np][ss + 1]);
                }
        }
    }

#pragma unroll
    for (int mt = 0; mt < 4; mt++) {
#pragma unroll
        for (int p = 0; p < 2; p++) {
            int lrow2 = wm + mt * 16 + (lane >> 2) + p * 8;
            size_t gr = ((size_t)e * cT + m0 + lrow2) * (size_t)Ntot;
#pragma unroll
            for (int nt = 0; nt < 4; nt++) {
                int lcol = wn + nt * 8 + (lane & 3) * 2;
                *(float2*)(out + gr + n0 + lcol) =
                    make_float2(acc[mt][nt][p * 2], acc[mt][nt][p * 2 + 1]);
            }
        }
    }
}

// ---------------------------------------------------------------- host
static inline void* symaddr(const void* s) {
    void* p = nullptr;
    cudaGetSymbolAddress(&p, s);
    return p;
}

extern "C" void kernel_launch(void* const* d_in, const int* in_sizes, int n_in,
                              void* d_out, int out_size) {
    (void)in_sizes; (void)n_in; (void)out_size;
    const float* x  = (const float*)d_in[0];
    const float* w1 = (const float*)d_in[1];
    const float* w2 = (const float*)d_in[2];
    const float* w3 = (const float*)d_in[3];
    float* out = (float*)d_out;

    __half* xh  = (__half*)symaddr(g_x);
    __half* w1t = (__half*)symaddr(g_w1t);
    __half* w3t = (__half*)symaddr(g_w3t);
    __half* w2t = (__half*)symaddr(g_w2t);
    __half* h   = (__half*)symaddr(g_h);

    cudaFuncSetAttribute(dual_gemm_kernel, cudaFuncAttributeMaxDynamicSharedMemorySize, SMEM_F);
    cudaFuncSetAttribute(out_gemm_kernel, cudaFuncAttributeMaxDynamicSharedMemorySize, SMEM_O);

    // 1) x -> fp16
    cvt_x_kernel<<<(int)(X_ELEMS / 4 / 256), 256>>>((const float4*)x);
    // 2-4) transpose weights to K-major fp16 (64r x 32c tiles)
    cvt_tr_kernel<<<dim3(cH / 32, cD / 64, cE), 256>>>(w1, 0, cD, cH);
    cvt_tr_kernel<<<dim3(cH / 32, cD / 64, cE), 256>>>(w3, 1, cD, cH);
    cvt_tr_kernel<<<dim3(cD / 32, cH / 64, cE), 256>>>(w2, 2, cH, cD);
    // 5) fused: G = x@w1, U = x@w3, h = silu(G)*U -> fp16 (2 CTAs/SM)
    dual_gemm_kernel<<<dim3(cH / 64, cT / 128, cE), 128, SMEM_F>>>(
        xh, w1t, w3t, h);
    // 6) out = h @ w2 (fp32)
    out_gemm_kernel<<<dim3(cD / 128, cT / 128, cE), 256, SMEM_O>>>(
        h, w2t, out);
}

// round 15
// speedup vs baseline: 1.1638x; 1.1441x over previous
#include <cuda_runtime.h>
#include <cuda_fp16.h>
#include <cstdint>
#include <cstddef>

// ---------------------------------------------------------------- constants
constexpr int cE = 8, cT = 4096, cD = 2048, cH = 1024;
constexpr size_t X_ELEMS = (size_t)cE * cT * cD;
constexpr size_t W_ELEMS = (size_t)cE * cD * cH;
constexpr size_t H_ELEMS = (size_t)cE * cT * cH;

// ---------------------------------------------------------------- scratch
__device__ __align__(16) __half g_x[X_ELEMS];     // [E][T][D] fp16(x)
__device__ __align__(16) __half g_w1t[W_ELEMS];   // [E][H][D] fp16(w1^T)
__device__ __align__(16) __half g_w3t[W_ELEMS];   // [E][H][D] fp16(w3^T)
__device__ __align__(16) __half g_w2t[W_ELEMS];   // [E][D][H] fp16(w2^T)
__device__ __align__(16) __half g_h[H_ELEMS];     // [E][T][H] fp16(h)

// ---------------------------------------------------------------- PTX helpers
__device__ __forceinline__ uint32_t smem_u32(const void* p) {
    return (uint32_t)__cvta_generic_to_shared(p);
}
__device__ __forceinline__ void cp16(uint32_t dst, const void* src) {
    asm volatile("cp.async.cg.shared.global [%0], [%1], 16;"
                 :: "r"(dst), "l"(src) : "memory");
}
__device__ __forceinline__ void cp_commit() {
    asm volatile("cp.async.commit_group;" ::: "memory");
}
template <int N> __device__ __forceinline__ void cp_wait() {
    asm volatile("cp.async.wait_group %0;" :: "n"(N) : "memory");
}
__device__ __forceinline__ void ldsm4(uint32_t* r, uint32_t addr) {
    asm volatile("ldmatrix.sync.aligned.m8n8.x4.shared.b16 {%0,%1,%2,%3}, [%4];"
                 : "=r"(r[0]), "=r"(r[1]), "=r"(r[2]), "=r"(r[3]) : "r"(addr));
}
__device__ __forceinline__ void mma16816(float* d, const uint32_t* a,
                                         uint32_t b0, uint32_t b1) {
    asm volatile(
        "mma.sync.aligned.m16n8k16.row.col.f32.f16.f16.f32 "
        "{%0,%1,%2,%3}, {%4,%5,%6,%7}, {%8,%9}, {%0,%1,%2,%3};"
        : "+f"(d[0]), "+f"(d[1]), "+f"(d[2]), "+f"(d[3])
        : "r"(a[0]), "r"(a[1]), "r"(a[2]), "r"(a[3]), "r"(b0), "r"(b1));
}
#define SWZ(o) ((o) ^ (((o) >> 3) & 0x70))

// ---------------------------------------------------------------- conversions
__global__ void cvt_x_kernel(const float4* __restrict__ x) {
    size_t i = (size_t)blockIdx.x * blockDim.x + threadIdx.x;
    if (i >= X_ELEMS / 4) return;
    float4 v = x[i];
    uint2 o;
    o.x = ((uint32_t)__half_as_ushort(__float2half(v.y)) << 16)
        | __half_as_ushort(__float2half(v.x));
    o.y = ((uint32_t)__half_as_ushort(__float2half(v.w)) << 16)
        | __half_as_ushort(__float2half(v.z));
    ((uint2*)g_x)[i] = o;
}

// transpose: w [E][R][C] f32 -> out [E][C][R] fp16.
// 64(r) x 32(c) tiles; coalesced 128B loads AND 128B half2 stores.
__global__ void cvt_tr_kernel(const float* __restrict__ w, int which, int R, int C) {
    __shared__ float tile[64][33];
    int e = blockIdx.z;
    int c0 = blockIdx.x * 32, r0 = blockIdx.y * 64;
    int tx = threadIdx.x & 31, ty = threadIdx.x >> 5;   // 256 threads
    const float* wp = w + (size_t)e * R * C;
#pragma unroll
    for (int i = ty; i < 64; i += 8)
        tile[i][tx] = wp[(size_t)(r0 + i) * C + c0 + tx];
    __syncthreads();
    __half* oh = (which == 0) ? g_w1t : (which == 1) ? g_w3t : g_w2t;
    oh += (size_t)e * C * R;
    int cc = threadIdx.x >> 5;   // 0..7
    int r2 = threadIdx.x & 31;   // half2 index over 64 rows
#pragma unroll
    for (int j = 0; j < 4; j++) {
        int c = cc + j * 8;
        __half2 v = __floats2half2_rn(tile[2 * r2][c], tile[2 * r2 + 1][c]);
        *(__half2*)(oh + (size_t)(c0 + c) * R + r0 + 2 * r2) = v;
    }
}

// ---------------------------------------------------------------- fused dual GEMM
// (R10 configuration) CTA 128x128, 256 threads, 4 stages x 48 KB, 1 CTA/SM.
// G = x@w1, U = x@w3 (pure fp16), h = silu(G)*U -> fp16.
constexpr int TILE_B = 128 * 128;            // 128 rows x 128 bytes (64 halfs)
constexpr int STAGES_F = 4;
constexpr int STAGE_F_B = 3 * TILE_B;        // A, B1, B3 = 48 KB
constexpr int SMEM_F = STAGES_F * STAGE_F_B; // 192 KB

__global__ void __launch_bounds__(256, 1) dual_gemm_kernel(
    const __half* __restrict__ A,
    const __half* __restrict__ B1, const __half* __restrict__ B3,
    __half* __restrict__ hout)
{
    constexpr int K = cD, Ntot = cH;
    extern __shared__ __align__(1024) char smraw[];
    const uint32_t smem = smem_u32(smraw);
    const int tid = threadIdx.x;
    const int lane = tid & 31, w = tid >> 5;
    const int wm = (w >> 2) * 64;
    const int wn = (w & 3) * 32;
    const int n0 = blockIdx.x * 128, m0 = blockIdx.y * 128, e = blockIdx.z;

    const int lr = tid >> 1;
    const int lhB = (tid & 1) * 64;
    const __half* aH = A + ((size_t)e * cT + m0 + lr) * K + (lhB >> 1);
    const __half* b1 = B1 + ((size_t)e * Ntot + n0 + lr) * K + (lhB >> 1);
    const __half* b3 = B3 + ((size_t)e * Ntot + n0 + lr) * K + (lhB >> 1);
    const uint32_t lrow = (uint32_t)lr * 128u + (uint32_t)lhB;
    const int nK = K / 64;   // 32

    auto load_stage = [&](int s, int k) {
        uint32_t base = smem + s * STAGE_F_B;
        int k0 = k * 64;
#pragma unroll
        for (int j = 0; j < 4; j++) {
            uint32_t sw = SWZ(lrow + j * 16);
            cp16(base              + sw, aH + k0 + j * 8);
            cp16(base + TILE_B     + sw, b1 + k0 + j * 8);
            cp16(base + 2 * TILE_B + sw, b3 + k0 + j * 8);
        }
    };

    const uint32_t arow = (uint32_t)(lane & 15);
    const uint32_t akb  = (uint32_t)((lane >> 4) * 16);
    const uint32_t brow = (uint32_t)((lane & 7) + ((lane & 16) >> 1));
    const uint32_t bkb  = (uint32_t)(((lane & 8) >> 3) * 16);

    float accG[4][4][4] = {};
    float accU[4][4][4] = {};

#pragma unroll
    for (int s = 0; s < STAGES_F - 1; s++) { load_stage(s, s); cp_commit(); }

    for (int kk = 0; kk < nK; kk++) {
        int s = kk % STAGES_F;
        cp_wait<STAGES_F - 2>();
        __syncthreads();
        if (kk + STAGES_F - 1 < nK)
            load_stage((kk + STAGES_F - 1) % STAGES_F, kk + STAGES_F - 1);
        cp_commit();
        uint32_t base = smem + s * STAGE_F_B;
#pragma unroll
        for (int ks = 0; ks < 4; ks++) {
            uint32_t Ah[4][4], Bf[2][4];
#pragma unroll
            for (int mt = 0; mt < 4; mt++) {
                uint32_t off = SWZ((uint32_t)(wm + mt * 16 + arow) * 128u + ks * 32 + akb);
                ldsm4(Ah[mt], base + off);
            }
            // --- G path (w1)
#pragma unroll
            for (int np = 0; np < 2; np++) {
                uint32_t off = SWZ((uint32_t)(wn + np * 16 + brow) * 128u + ks * 32 + bkb);
                ldsm4(Bf[np], base + TILE_B + off);
            }
#pragma unroll
            for (int mt = 0; mt < 4; mt++)
#pragma unroll
                for (int nt = 0; nt < 4; nt++) {
                    int np = nt >> 1, ss = (nt & 1) * 2;
                    mma16816(accG[mt][nt], Ah[mt], Bf[np][ss], Bf[np][ss + 1]);
                }
            // --- U path (w3)
#pragma unroll
            for (int np = 0; np < 2; np++) {
                uint32_t off = SWZ((uint32_t)(wn + np * 16 + brow) * 128u + ks * 32 + bkb);
                ldsm4(Bf[np], base + 2 * TILE_B + off);
            }
#pragma unroll
            for (int mt = 0; mt < 4; mt++)
#pragma unroll
                for (int nt = 0; nt < 4; nt++) {
                    int np = nt >> 1, ss = (nt & 1) * 2;
                    mma16816(accU[mt][nt], Ah[mt], Bf[np][ss], Bf[np][ss + 1]);
                }
        }
    }

    // --- epilogue: h = silu(G) * U -> fp16
#pragma unroll
    for (int mt = 0; mt < 4; mt++) {
#pragma unroll
        for (int p = 0; p < 2; p++) {
            int lrow2 = wm + mt * 16 + (lane >> 2) + p * 8;
            size_t gr = ((size_t)e * cT + m0 + lrow2) * (size_t)Ntot;
#pragma unroll
            for (int nt = 0; nt < 4; nt++) {
                int lcol = wn + nt * 8 + (lane & 3) * 2;
                size_t idx = gr + n0 + lcol;
                float gv0 = accG[mt][nt][p * 2], gv1 = accG[mt][nt][p * 2 + 1];
                float uv0 = accU[mt][nt][p * 2], uv1 = accU[mt][nt][p * 2 + 1];
                float h0 = uv0 * gv0 / (1.0f + __expf(-gv0));
                float h1 = uv1 * gv1 / (1.0f + __expf(-gv1));
                __half2 vh;
                vh.x = __float2half(h0);
                vh.y = __float2half(h1);
                *(__half2*)(hout + idx) = vh;
            }
        }
    }
}

// ---------------------------------------------------------------- out GEMM
// (R10 configuration) out = h @ w2, 3 stages x 32 KB, 2 CTAs/SM.
constexpr int STAGES_O = 3;
constexpr int STAGE_O_B = 2 * TILE_B;        // A, B = 32 KB
constexpr int SMEM_O = STAGES_O * STAGE_O_B; // 96 KB

__global__ void __launch_bounds__(256, 2) out_gemm_kernel(
    const __half* __restrict__ A, const __half* __restrict__ B,
    float* __restrict__ out)
{
    constexpr int K = cH, Ntot = cD;
    extern __shared__ __align__(1024) char smraw[];
    const uint32_t smem = smem_u32(smraw);
    const int tid = threadIdx.x;
    const int lane = tid & 31, w = tid >> 5;
    const int wm = (w >> 2) * 64;
    const int wn = (w & 3) * 32;
    const int n0 = blockIdx.x * 128, m0 = blockIdx.y * 128, e = blockIdx.z;

    const int lr = tid >> 1;
    const int lhB = (tid & 1) * 64;
    const __half* aH = A + ((size_t)e * cT + m0 + lr) * K + (lhB >> 1);
    const __half* bH = B + ((size_t)e * Ntot + n0 + lr) * K + (lhB >> 1);
    const uint32_t lrow = (uint32_t)lr * 128u + (uint32_t)lhB;
    const int nK = K / 64;   // 16

    auto load_stage = [&](int s, int k) {
        uint32_t base = smem + s * STAGE_O_B;
        int k0 = k * 64;
#pragma unroll
        for (int j = 0; j < 4; j++) {
            uint32_t sw = SWZ(lrow + j * 16);
            cp16(base          + sw, aH + k0 + j * 8);
            cp16(base + TILE_B + sw, bH + k0 + j * 8);
        }
    };

    const uint32_t arow = (uint32_t)(lane & 15);
    const uint32_t akb  = (uint32_t)((lane >> 4) * 16);
    const uint32_t brow = (uint32_t)((lane & 7) + ((lane & 16) >> 1));
    const uint32_t bkb  = (uint32_t)(((lane & 8) >> 3) * 16);

    float acc[4][4][4] = {};

#pragma unroll
    for (int s = 0; s < STAGES_O - 1; s++) { load_stage(s, s); cp_commit(); }

    for (int kk = 0; kk < nK; kk++) {
        int s = kk % STAGES_O;
        cp_wait<STAGES_O - 2>();
        __syncthreads();
        if (kk + STAGES_O - 1 < nK)
            load_stage((kk + STAGES_O - 1) % STAGES_O, kk + STAGES_O - 1);
        cp_commit();
        uint32_t base = smem + s * STAGE_O_B;
#pragma unroll
        for (int ks = 0; ks < 4; ks++) {
            uint32_t Ah[4][4], Bh[2][4];
#pragma unroll
            for (int mt = 0; mt < 4; mt++) {
                uint32_t off = SWZ((uint32_t)(wm + mt * 16 + arow) * 128u + ks * 32 + akb);
                ldsm4(Ah[mt], base + off);
            }
#pragma unroll
            for (int np = 0; np < 2; np++) {
                uint32_t off = SWZ((uint32_t)(wn + np * 16 + brow) * 128u + ks * 32 + bkb);
                ldsm4(Bh[np], base + TILE_B + off);
            }
#pragma unroll
            for (int mt = 0; mt < 4; mt++)
#pragma unroll
                for (int nt = 0; nt < 4; nt++) {
                    int np = nt >> 1, ss = (nt & 1) * 2;
                    mma16816(acc[mt][nt], Ah[mt], Bh[np][ss], Bh[np][ss + 1]);
                }
        }
    }

#pragma unroll
    for (int mt = 0; mt < 4; mt++) {
#pragma unroll
        for (int p = 0; p < 2; p++) {
            int lrow2 = wm + mt * 16 + (lane >> 2) + p * 8;
            size_t gr = ((size_t)e * cT + m0 + lrow2) * (size_t)Ntot;
#pragma unroll
            for (int nt = 0; nt < 4; nt++) {
                int lcol = wn + nt * 8 + (lane & 3) * 2;
                *(float2*)(out + gr + n0 + lcol) =
                    make_float2(acc[mt][nt][p * 2], acc[mt][nt][p * 2 + 1]);
            }
        }
    }
}

// ---------------------------------------------------------------- host
static inline void* symaddr(const void* s) {
    void* p = nullptr;
    cudaGetSymbolAddress(&p, s);
    return p;
}

extern "C" void kernel_launch(void* const* d_in, const int* in_sizes, int n_in,
                              void* d_out, int out_size) {
    (void)in_sizes; (void)n_in; (void)out_size;
    const float* x  = (const float*)d_in[0];
    const float* w1 = (const float*)d_in[1];
    const float* w2 = (const float*)d_in[2];
    const float* w3 = (const float*)d_in[3];
    float* out = (float*)d_out;

    __half* xh  = (__half*)symaddr(g_x);
    __half* w1t = (__half*)symaddr(g_w1t);
    __half* w3t = (__half*)symaddr(g_w3t);
    __half* w2t = (__half*)symaddr(g_w2t);
    __half* h   = (__half*)symaddr(g_h);

    cudaFuncSetAttribute(dual_gemm_kernel, cudaFuncAttributeMaxDynamicSharedMemorySize, SMEM_F);
    cudaFuncSetAttribute(out_gemm_kernel, cudaFuncAttributeMaxDynamicSharedMemorySize, SMEM_O);

    // 1) x -> fp16
    cvt_x_kernel<<<(int)(X_ELEMS / 4 / 256), 256>>>((const float4*)x);
    // 2-4) transpose weights to K-major fp16 (64r x 32c tiles, fast stores)
    cvt_tr_kernel<<<dim3(cH / 32, cD / 64, cE), 256>>>(w1, 0, cD, cH);
    cvt_tr_kernel<<<dim3(cH / 32, cD / 64, cE), 256>>>(w3, 1, cD, cH);
    cvt_tr_kernel<<<dim3(cD / 32, cH / 64, cE), 256>>>(w2, 2, cH, cD);
    // 5) fused: G = x@w1, U = x@w3, h = silu(G)*U -> fp16
    dual_gemm_kernel<<<dim3(cH / 128, cT / 128, cE), 256, SMEM_F>>>(
        xh, w1t, w3t, h);
    // 6) out = h @ w2 (fp32)
    out_gemm_kernel<<<dim3(cD / 128, cT / 128, cE), 256, SMEM_O>>>(
        h, w2t, out);
}

// round 16
// speedup vs baseline: 1.1779x; 1.0121x over previous
#include <cuda_runtime.h>
#include <cuda_fp16.h>
#include <cstdint>
#include <cstddef>

// ---------------------------------------------------------------- constants
constexpr int cE = 8, cT = 4096, cD = 2048, cH = 1024;
constexpr size_t X_ELEMS = (size_t)cE * cT * cD;
constexpr size_t W_ELEMS = (size_t)cE * cD * cH;
constexpr size_t H_ELEMS = (size_t)cE * cT * cH;

// ---------------------------------------------------------------- scratch
__device__ __align__(16) __half g_x[X_ELEMS];     // [E][T][D] fp16(x)
__device__ __align__(16) __half g_w1t[W_ELEMS];   // [E][H][D] fp16(w1^T)
__device__ __align__(16) __half g_w3t[W_ELEMS];   // [E][H][D] fp16(w3^T)
__device__ __align__(16) __half g_w2t[W_ELEMS];   // [E][D][H] fp16(w2^T)
__device__ __align__(16) __half g_h[H_ELEMS];     // [E][T][H] fp16(h)

// ---------------------------------------------------------------- PTX helpers
__device__ __forceinline__ uint32_t smem_u32(const void* p) {
    return (uint32_t)__cvta_generic_to_shared(p);
}
__device__ __forceinline__ void cp16(uint32_t dst, const void* src) {
    asm volatile("cp.async.cg.shared.global [%0], [%1], 16;"
                 :: "r"(dst), "l"(src) : "memory");
}
__device__ __forceinline__ void cp_commit() {
    asm volatile("cp.async.commit_group;" ::: "memory");
}
template <int N> __device__ __forceinline__ void cp_wait() {
    asm volatile("cp.async.wait_group %0;" :: "n"(N) : "memory");
}
__device__ __forceinline__ void ldsm4(uint32_t* r, uint32_t addr) {
    asm volatile("ldmatrix.sync.aligned.m8n8.x4.shared.b16 {%0,%1,%2,%3}, [%4];"
                 : "=r"(r[0]), "=r"(r[1]), "=r"(r[2]), "=r"(r[3]) : "r"(addr));
}
__device__ __forceinline__ void mma16816(float* d, const uint32_t* a,
                                         uint32_t b0, uint32_t b1) {
    asm volatile(
        "mma.sync.aligned.m16n8k16.row.col.f32.f16.f16.f32 "
        "{%0,%1,%2,%3}, {%4,%5,%6,%7}, {%8,%9}, {%0,%1,%2,%3};"
        : "+f"(d[0]), "+f"(d[1]), "+f"(d[2]), "+f"(d[3])
        : "r"(a[0]), "r"(a[1]), "r"(a[2]), "r"(a[3]), "r"(b0), "r"(b1));
}
#define SWZ(o) ((o) ^ (((o) >> 3) & 0x70))

// ---------------------------------------------------------------- conversions
__global__ void cvt_x_kernel(const float4* __restrict__ x) {
    size_t i = (size_t)blockIdx.x * blockDim.x + threadIdx.x;
    if (i >= X_ELEMS / 4) return;
    float4 v = x[i];
    uint2 o;
    o.x = ((uint32_t)__half_as_ushort(__float2half(v.y)) << 16)
        | __half_as_ushort(__float2half(v.x));
    o.y = ((uint32_t)__half_as_ushort(__float2half(v.w)) << 16)
        | __half_as_ushort(__float2half(v.z));
    ((uint2*)g_x)[i] = o;
}

// merged transpose: all three weights in one launch.
// blockIdx.y = which (0:w1, 1:w3, 2:w2), blockIdx.z = expert,
// blockIdx.x = flattened tile index (1024 tiles for both shapes).
// w [E][R][C] f32 -> out [E][C][R] fp16; 64(r) x 32(c) tiles, coalesced both ways.
__global__ void cvt_tr_all_kernel(const float* __restrict__ w1,
                                  const float* __restrict__ w3,
                                  const float* __restrict__ w2) {
    __shared__ float tile[64][33];
    const int which = blockIdx.y;
    const int e = blockIdx.z;
    const int R = (which == 2) ? cH : cD;
    const int C = (which == 2) ? cD : cH;
    const int tiles_x = C / 32;
    const int c0 = (blockIdx.x % tiles_x) * 32;
    const int r0 = (blockIdx.x / tiles_x) * 64;
    const float* w = (which == 0) ? w1 : (which == 1) ? w3 : w2;
    int tx = threadIdx.x & 31, ty = threadIdx.x >> 5;   // 256 threads
    const float* wp = w + (size_t)e * R * C;
#pragma unroll
    for (int i = ty; i < 64; i += 8)
        tile[i][tx] = wp[(size_t)(r0 + i) * C + c0 + tx];
    __syncthreads();
    __half* oh = (which == 0) ? g_w1t : (which == 1) ? g_w3t : g_w2t;
    oh += (size_t)e * C * R;
    int cc = threadIdx.x >> 5;   // 0..7
    int r2 = threadIdx.x & 31;   // half2 index over 64 rows
#pragma unroll
    for (int j = 0; j < 4; j++) {
        int c = cc + j * 8;
        __half2 v = __floats2half2_rn(tile[2 * r2][c], tile[2 * r2 + 1][c]);
        *(__half2*)(oh + (size_t)(c0 + c) * R + r0 + 2 * r2) = v;
    }
}

// ---------------------------------------------------------------- fused dual GEMM
// CTA 128x128, 256 threads, 4 stages x 48 KB, 1 CTA/SM.
// G = x@w1, U = x@w3 (pure fp16), h = silu(G)*U -> fp16.
// B1 and B3 fragments both loaded up-front per ks so U-path MMAs never
// wait on a just-issued ldsm (B3 latency buried under the 16 G MMAs).
constexpr int TILE_B = 128 * 128;            // 128 rows x 128 bytes (64 halfs)
constexpr int STAGES_F = 4;
constexpr int STAGE_F_B = 3 * TILE_B;        // A, B1, B3 = 48 KB
constexpr int SMEM_F = STAGES_F * STAGE_F_B; // 192 KB

__global__ void __launch_bounds__(256, 1) dual_gemm_kernel(
    const __half* __restrict__ A,
    const __half* __restrict__ B1, const __half* __restrict__ B3,
    __half* __restrict__ hout)
{
    constexpr int K = cD, Ntot = cH;
    extern __shared__ __align__(1024) char smraw[];
    const uint32_t smem = smem_u32(smraw);
    const int tid = threadIdx.x;
    const int lane = tid & 31, w = tid >> 5;
    const int wm = (w >> 2) * 64;
    const int wn = (w & 3) * 32;
    const int n0 = blockIdx.x * 128, m0 = blockIdx.y * 128, e = blockIdx.z;

    const int lr = tid >> 1;
    const int lhB = (tid & 1) * 64;
    const __half* aH = A + ((size_t)e * cT + m0 + lr) * K + (lhB >> 1);
    const __half* b1 = B1 + ((size_t)e * Ntot + n0 + lr) * K + (lhB >> 1);
    const __half* b3 = B3 + ((size_t)e * Ntot + n0 + lr) * K + (lhB >> 1);
    const uint32_t lrow = (uint32_t)lr * 128u + (uint32_t)lhB;
    const int nK = K / 64;   // 32

    auto load_stage = [&](int s, int k) {
        uint32_t base = smem + s * STAGE_F_B;
        int k0 = k * 64;
#pragma unroll
        for (int j = 0; j < 4; j++) {
            uint32_t sw = SWZ(lrow + j * 16);
            cp16(base              + sw, aH + k0 + j * 8);
            cp16(base + TILE_B     + sw, b1 + k0 + j * 8);
            cp16(base + 2 * TILE_B + sw, b3 + k0 + j * 8);
        }
    };

    const uint32_t arow = (uint32_t)(lane & 15);
    const uint32_t akb  = (uint32_t)((lane >> 4) * 16);
    const uint32_t brow = (uint32_t)((lane & 7) + ((lane & 16) >> 1));
    const uint32_t bkb  = (uint32_t)(((lane & 8) >> 3) * 16);

    float accG[4][4][4] = {};
    float accU[4][4][4] = {};

#pragma unroll
    for (int s = 0; s < STAGES_F - 1; s++) { load_stage(s, s); cp_commit(); }

    for (int kk = 0; kk < nK; kk++) {
        int s = kk % STAGES_F;
        cp_wait<STAGES_F - 2>();
        __syncthreads();
        if (kk + STAGES_F - 1 < nK)
            load_stage((kk + STAGES_F - 1) % STAGES_F, kk + STAGES_F - 1);
        cp_commit();
        uint32_t base = smem + s * STAGE_F_B;
#pragma unroll
        for (int ks = 0; ks < 4; ks++) {
            uint32_t Ah[4][4], B1f[2][4], B3f[2][4];
#pragma unroll
            for (int mt = 0; mt < 4; mt++) {
                uint32_t off = SWZ((uint32_t)(wm + mt * 16 + arow) * 128u + ks * 32 + akb);
                ldsm4(Ah[mt], base + off);
            }
#pragma unroll
            for (int np = 0; np < 2; np++) {
                uint32_t off = SWZ((uint32_t)(wn + np * 16 + brow) * 128u + ks * 32 + bkb);
                ldsm4(B1f[np], base + TILE_B + off);
                ldsm4(B3f[np], base + 2 * TILE_B + off);
            }
            // --- G path (w1): covers B3f latency
#pragma unroll
            for (int mt = 0; mt < 4; mt++)
#pragma unroll
                for (int nt = 0; nt < 4; nt++) {
                    int np = nt >> 1, ss = (nt & 1) * 2;
                    mma16816(accG[mt][nt], Ah[mt], B1f[np][ss], B1f[np][ss + 1]);
                }
            // --- U path (w3)
#pragma unroll
            for (int mt = 0; mt < 4; mt++)
#pragma unroll
                for (int nt = 0; nt < 4; nt++) {
                    int np = nt >> 1, ss = (nt & 1) * 2;
                    mma16816(accU[mt][nt], Ah[mt], B3f[np][ss], B3f[np][ss + 1]);
                }
        }
    }

    // --- epilogue: h = silu(G) * U -> fp16
#pragma unroll
    for (int mt = 0; mt < 4; mt++) {
#pragma unroll
        for (int p = 0; p < 2; p++) {
            int lrow2 = wm + mt * 16 + (lane >> 2) + p * 8;
            size_t gr = ((size_t)e * cT + m0 + lrow2) * (size_t)Ntot;
#pragma unroll
            for (int nt = 0; nt < 4; nt++) {
                int lcol = wn + nt * 8 + (lane & 3) * 2;
                size_t idx = gr + n0 + lcol;
                float gv0 = accG[mt][nt][p * 2], gv1 = accG[mt][nt][p * 2 + 1];
                float uv0 = accU[mt][nt][p * 2], uv1 = accU[mt][nt][p * 2 + 1];
                float h0 = uv0 * gv0 / (1.0f + __expf(-gv0));
                float h1 = uv1 * gv1 / (1.0f + __expf(-gv1));
                __half2 vh;
                vh.x = __float2half(h0);
                vh.y = __float2half(h1);
                *(__half2*)(hout + idx) = vh;
            }
        }
    }
}

// ---------------------------------------------------------------- out GEMM
// out = h @ w2, pure fp16, fp32 out. 3 stages x 32 KB, 2 CTAs/SM.
constexpr int STAGES_O = 3;
constexpr int STAGE_O_B = 2 * TILE_B;        // A, B = 32 KB
constexpr int SMEM_O = STAGES_O * STAGE_O_B; // 96 KB

__global__ void __launch_bounds__(256, 2) out_gemm_kernel(
    const __half* __restrict__ A, const __half* __restrict__ B,
    float* __restrict__ out)
{
    constexpr int K = cH, Ntot = cD;
    extern __shared__ __align__(1024) char smraw[];
    const uint32_t smem = smem_u32(smraw);
    const int tid = threadIdx.x;
    const int lane = tid & 31, w = tid >> 5;
    const int wm = (w >> 2) * 64;
    const int wn = (w & 3) * 32;
    const int n0 = blockIdx.x * 128, m0 = blockIdx.y * 128, e = blockIdx.z;

    const int lr = tid >> 1;
    const int lhB = (tid & 1) * 64;
    const __half* aH = A + ((size_t)e * cT + m0 + lr) * K + (lhB >> 1);
    const __half* bH = B + ((size_t)e * Ntot + n0 + lr) * K + (lhB >> 1);
    const uint32_t lrow = (uint32_t)lr * 128u + (uint32_t)lhB;
    const int nK = K / 64;   // 16

    auto load_stage = [&](int s, int k) {
        uint32_t base = smem + s * STAGE_O_B;
        int k0 = k * 64;
#pragma unroll
        for (int j = 0; j < 4; j++) {
            uint32_t sw = SWZ(lrow + j * 16);
            cp16(base          + sw, aH + k0 + j * 8);
            cp16(base + TILE_B + sw, bH + k0 + j * 8);
        }
    };

    const uint32_t arow = (uint32_t)(lane & 15);
    const uint32_t akb  = (uint32_t)((lane >> 4) * 16);
    const uint32_t brow = (uint32_t)((lane & 7) + ((lane & 16) >> 1));
    const uint32_t bkb  = (uint32_t)(((lane & 8) >> 3) * 16);

    float acc[4][4][4] = {};

#pragma unroll
    for (int s = 0; s < STAGES_O - 1; s++) { load_stage(s, s); cp_commit(); }

    for (int kk = 0; kk < nK; kk++) {
        int s = kk % STAGES_O;
        cp_wait<STAGES_O - 2>();
        __syncthreads();
        if (kk + STAGES_O - 1 < nK)
            load_stage((kk + STAGES_O - 1) % STAGES_O, kk + STAGES_O - 1);
        cp_commit();
        uint32_t base = smem + s * STAGE_O_B;
#pragma unroll
        for (int ks = 0; ks < 4; ks++) {
            uint32_t Ah[4][4], Bh[2][4];
#pragma unroll
            for (int mt = 0; mt < 4; mt++) {
                uint32_t off = SWZ((uint32_t)(wm + mt * 16 + arow) * 128u + ks * 32 + akb);
                ldsm4(Ah[mt], base + off);
            }
#pragma unroll
            for (int np = 0; np < 2; np++) {
                uint32_t off = SWZ((uint32_t)(wn + np * 16 + brow) * 128u + ks * 32 + bkb);
                ldsm4(Bh[np], base + TILE_B + off);
            }
#pragma unroll
            for (int mt = 0; mt < 4; mt++)
#pragma unroll
                for (int nt = 0; nt < 4; nt++) {
                    int np = nt >> 1, ss = (nt & 1) * 2;
                    mma16816(acc[mt][nt], Ah[mt], Bh[np][ss], Bh[np][ss + 1]);
                }
        }
    }

#pragma unroll
    for (int mt = 0; mt < 4; mt++) {
#pragma unroll
        for (int p = 0; p < 2; p++) {
            int lrow2 = wm + mt * 16 + (lane >> 2) + p * 8;
            size_t gr = ((size_t)e * cT + m0 + lrow2) * (size_t)Ntot;
#pragma unroll
            for (int nt = 0; nt < 4; nt++) {
                int lcol = wn + nt * 8 + (lane & 3) * 2;
                *(float2*)(out + gr + n0 + lcol) =
                    make_float2(acc[mt][nt][p * 2], acc[mt][nt][p * 2 + 1]);
            }
        }
    }
}

// ---------------------------------------------------------------- host
static inline void* symaddr(const void* s) {
    void* p = nullptr;
    cudaGetSymbolAddress(&p, s);
    return p;
}

extern "C" void kernel_launch(void* const* d_in, const int* in_sizes, int n_in,
                              void* d_out, int out_size) {
    (void)in_sizes; (void)n_in; (void)out_size;
    const float* x  = (const float*)d_in[0];
    const float* w1 = (const float*)d_in[1];
    const float* w2 = (const float*)d_in[2];
    const float* w3 = (const float*)d_in[3];
    float* out = (float*)d_out;

    __half* xh  = (__half*)symaddr(g_x);
    __half* w1t = (__half*)symaddr(g_w1t);
    __half* w3t = (__half*)symaddr(g_w3t);
    __half* w2t = (__half*)symaddr(g_w2t);
    __half* h   = (__half*)symaddr(g_h);

    cudaFuncSetAttribute(dual_gemm_kernel, cudaFuncAttributeMaxDynamicSharedMemorySize, SMEM_F);
    cudaFuncSetAttribute(out_gemm_kernel, cudaFuncAttributeMaxDynamicSharedMemorySize, SMEM_O);

    // 1) x -> fp16
    cvt_x_kernel<<<(int)(X_ELEMS / 4 / 256), 256>>>((const float4*)x);
    // 2) all three weight transposes in one launch
    cvt_tr_all_kernel<<<dim3(1024, 3, cE), 256>>>(w1, w3, w2);
    // 3) fused: G = x@w1, U = x@w3, h = silu(G)*U -> fp16
    dual_gemm_kernel<<<dim3(cH / 128, cT / 128, cE), 256, SMEM_F>>>(
        xh, w1t, w3t, h);
    // 4) out = h @ w2 (fp32)
    out_gemm_kernel<<<dim3(cD / 128, cT / 128, cE), 256, SMEM_O>>>(
        h, w2t, out);
}